// round 14
// baseline (speedup 1.0000x reference)
#include <cuda_runtime.h>
#include <cuda_bf16.h>

// ---------------------------------------------------------------------------
// VoxelHashTableDynamic fused kernel (fp32, packed f32x2 FMA path)
//
// Per CTA: 32 points, 2 CTAs/SM. All intermediates in smem, transposed
// layout [d][m] with row stride 34 floats (8B aligned pairs).
// Projection tiling: 240 active threads = 2 m-groups (16 pts each, as 8
// packed f32x2 pairs) x 120 j-columns (1 per thread). Each 4B weight load
// feeds 8 FMA2 -> 4x the MACs/byte of the previous (4m x 4j) tiling, which
// was L1-bandwidth bound (74.5% L1, 44.8% fma in R13).
// ---------------------------------------------------------------------------

#define PTS_PER_CTA 32
#define D_DIM       120
#define STRIDE      34            // padded row stride (even -> 8B aligned pairs)
#define BUF_FLOATS  (D_DIM * STRIDE)   // 4080
#define HEADS       8
#define HEAD_DIM    15
#define MOD_T       201
#define HASH_MASK   1048575LL
#define SMEM_BYTES  (7 * BUF_FLOATS * 4 + (3 * PTS_PER_CTA + 2) * 4)

__device__ __forceinline__ unsigned long long splat2(float x) {
    unsigned long long d;
    asm("mov.b64 %0, {%1, %1};" : "=l"(d) : "f"(x));
    return d;
}

__device__ __forceinline__ unsigned long long fma2(unsigned long long a,
                                                   unsigned long long b,
                                                   unsigned long long c) {
    unsigned long long d;
    asm("fma.rn.f32x2 %0, %1, %2, %3;" : "=l"(d) : "l"(a), "l"(b), "l"(c));
    return d;
}

__device__ __forceinline__ float2 unpack2(unsigned long long v) {
    float2 r;
    asm("mov.b64 {%0, %1}, %2;" : "=f"(r.x), "=f"(r.y) : "l"(v));
    return r;
}

// C_w[m][j0] = sum_k A[m][k] * W_w[k][j0] + B_w[j0], for w = 0..NW-1.
// The NW weight matrices are CONSECUTIVE (stride 14400 floats), biases
// consecutive (stride 120). A_T is smem transposed [k][m] (stride 34).
// Outputs written transposed [j][m] (stride 34).
// Thread tiling: mg = t/120 (2 groups of 16 m as 8 packed pairs),
//                j0 = t%120. Threads t>=240 must not call.
template <int NW>
__device__ __forceinline__ void proj_pass(const float* __restrict__ W,
                                          const float* __restrict__ Bi,
                                          const float* __restrict__ A_T,
                                          float* C0, float* C1, float* C2,
                                          int mg, int j0) {
    float* Cs[3] = {C0, C1, C2};
    const int m0 = mg * 16;

    unsigned long long acc[NW][8];
#pragma unroll
    for (int w = 0; w < NW; ++w) {
        unsigned long long b2 = splat2(Bi[w * 120 + j0]);
#pragma unroll
        for (int p = 0; p < 8; ++p) acc[w][p] = b2;
    }

    const float* wp = W + j0;

#pragma unroll 2
    for (int k = 0; k < D_DIM; ++k) {
        // weight prefetch for all NW matrices (independent LDGs, coalesced 4B)
        float wv[NW];
#pragma unroll
        for (int w = 0; w < NW; ++w) wv[w] = wp[w * 14400 + k * 120];

        unsigned long long a2[8];
        const float* arow = A_T + k * STRIDE + m0;
#pragma unroll
        for (int p = 0; p < 8; ++p)
            a2[p] = *reinterpret_cast<const unsigned long long*>(arow + 2 * p);

#pragma unroll
        for (int w = 0; w < NW; ++w) {
            unsigned long long ws = splat2(wv[w]);
#pragma unroll
            for (int p = 0; p < 8; ++p)
                acc[w][p] = fma2(a2[p], ws, acc[w][p]);
        }
    }

#pragma unroll
    for (int w = 0; w < NW; ++w)
#pragma unroll
        for (int p = 0; p < 8; ++p)
            *reinterpret_cast<unsigned long long*>(
                Cs[w] + j0 * STRIDE + m0 + 2 * p) = acc[w][p];
}

// Final projection: out[m][j0] = sum_k A[m][k]*W[k][j0] + B[j0], written
// straight to global memory with validity masking (invalid rows -> zeros).
// Per-warp lanes share m-set and have consecutive j0 -> coalesced STG.32.
__device__ __forceinline__ void proj_out_global(const float* __restrict__ W,
                                                const float* __restrict__ Bi,
                                                const float* __restrict__ A_T,
                                                float* __restrict__ out,
                                                int ctaBase, const int* val_s,
                                                int M, int mg, int j0) {
    const int m0 = mg * 16;

    unsigned long long acc[8];
    {
        unsigned long long b2 = splat2(Bi[j0]);
#pragma unroll
        for (int p = 0; p < 8; ++p) acc[p] = b2;
    }

    const float* wp = W + j0;

#pragma unroll 2
    for (int k = 0; k < D_DIM; ++k) {
        float wv = wp[k * 120];
        unsigned long long a2[8];
        const float* arow = A_T + k * STRIDE + m0;
#pragma unroll
        for (int p = 0; p < 8; ++p)
            a2[p] = *reinterpret_cast<const unsigned long long*>(arow + 2 * p);
        unsigned long long ws = splat2(wv);
#pragma unroll
        for (int p = 0; p < 8; ++p)
            acc[p] = fma2(a2[p], ws, acc[p]);
    }

#pragma unroll
    for (int p = 0; p < 8; ++p) {
        float2 v = unpack2(acc[p]);
        int mE = m0 + 2 * p;
        int mO = mE + 1;
        int gE = ctaBase + mE;
        int gO = ctaBase + mO;
        if (gE < M) out[(size_t)gE * 120 + j0] = val_s[mE] ? v.x : 0.0f;
        if (gO < M) out[(size_t)gO * 120 + j0] = val_s[mO] ? v.y : 0.0f;
    }
}

// 2-token attention: o0 = softmax([q0.k0, q0.k1]/sqrt(hd)) @ [v0; v1],
// per head, written back in place of PQ. 256 tasks = 32 points * 8 heads.
__device__ __forceinline__ void attention(float* PQ, const float* PK0,
                                          const float* PK1, const float* PV0,
                                          const float* PV1, int t) {
    const float SC = 0.25819888974716113f;  // 1/sqrt(15)
    int m = t & 31;
    int h = t >> 5;
    int base = h * HEAD_DIM;
    float s00 = 0.f, s01 = 0.f;
#pragma unroll
    for (int d = 0; d < HEAD_DIM; ++d) {
        int idx = (base + d) * STRIDE + m;
        float q = PQ[idx];
        s00 += q * PK0[idx];
        s01 += q * PK1[idx];
    }
    float p00 = 1.0f / (1.0f + __expf((s01 - s00) * SC));
    float p01 = 1.0f - p00;
#pragma unroll
    for (int d = 0; d < HEAD_DIM; ++d) {
        int idx = (base + d) * STRIDE + m;
        PQ[idx] = p00 * PV0[idx] + p01 * PV1[idx];
    }
}

__global__ __launch_bounds__(256, 2) void voxel_fused_kernel(
    const float* __restrict__ pts, const void* __restrict__ times_raw,
    const void* __restrict__ buf_raw, const float* __restrict__ statf,
    const float* __restrict__ dynf, const float* __restrict__ temb,
    const float* __restrict__ Wtd, const float* __restrict__ Btd,
    const float* __restrict__ Wsd, const float* __restrict__ Bsd,
    float* __restrict__ out, int M) {
    extern __shared__ float sm[];
    float* XA  = sm;
    float* XB  = sm + 1 * BUF_FLOATS;
    float* PQ  = sm + 2 * BUF_FLOATS;
    float* PK0 = sm + 3 * BUF_FLOATS;
    float* PK1 = sm + 4 * BUF_FLOATS;
    float* PV0 = sm + 5 * BUF_FLOATS;
    float* PV1 = sm + 6 * BUF_FLOATS;
    int* vi_s  = (int*)(sm + 7 * BUF_FLOATS);
    int* ti_s  = vi_s + PTS_PER_CTA;
    int* val_s = ti_s + PTS_PER_CTA;
    int* fl    = val_s + PTS_PER_CTA;   // fl[0]=buf is int32, fl[1]=times is int32

    const int t = threadIdx.x;
    const int ctaBase = blockIdx.x * PTS_PER_CTA;

    // ---- dtype probe: odd 32-bit words are sign/zero-extension iff int64 ----
    // Always in-bounds under either dtype (indices < element count).
    if (t < 2) fl[t] = 0;
    __syncthreads();
    if (t < 64) {
        const int* b32 = (const int*)buf_raw;
        int bad = 0;
#pragma unroll
        for (int r = 0; r < 2; ++r) {
            int w = b32[2 * (t + 64 * r) + 1];   // entries 1..255 odd / high words
            if (w != 0 && w != -1) bad = 1;
        }
        if (bad) atomicOr(&fl[0], 1);
        const int* q32 = (const int*)times_raw;
        int badt = 0;
#pragma unroll
        for (int r = 0; r < 4; ++r) {
            if (q32[2 * (t + 64 * r) + 1] != 0) badt = 1;
        }
        if (badt) atomicOr(&fl[1], 1);
    }
    __syncthreads();
    const bool buf32 = fl[0] != 0;
    const bool tim32 = fl[1] != 0;

    // ---- per-point metadata: hash lookup, validity, time index ----
    if (t < PTS_PER_CTA) {
        int g = ctaBase + t;
        int vi = 0, va = 0, ti = 0;
        if (g < M) {
            float px = pts[3 * g + 0];
            float py = pts[3 * g + 1];
            float pz = pts[3 * g + 2];
            // must match reference bit-for-bit: f32 IEEE divide, then floor
            long long g0 = (long long)floorf(__fdiv_rn(px, 0.1f));
            long long g1 = (long long)floorf(__fdiv_rn(py, 0.1f));
            long long g2 = (long long)floorf(__fdiv_rn(pz, 0.1f));
            long long h =
                (g0 * 73856093LL + g1 * 19349669LL + g2 * 83492791LL) & HASH_MASK;
            long long v = buf32 ? (long long)((const int*)buf_raw)[h]
                                : ((const long long*)buf_raw)[h];
            va = (v >= 0) ? 1 : 0;
            vi = va ? (int)v : 0;
            long long tv = tim32 ? (long long)((const int*)times_raw)[g]
                                 : ((const long long*)times_raw)[g];
            ti = (int)(tv % MOD_T);
            if (ti < 0) ti += MOD_T;
        }
        vi_s[t] = vi;
        ti_s[t] = ti;
        val_s[t] = va;
    }
    __syncthreads();

    // ---- gather dynamic features + time embeddings (transposed) ----
    for (int e = t; e < PTS_PER_CTA * D_DIM; e += 256) {
        int m = e / D_DIM;
        int d = e - m * D_DIM;
        XA[d * STRIDE + m] = dynf[(size_t)vi_s[m] * D_DIM + d];
        XB[d * STRIDE + m] = temb[(size_t)ti_s[m] * D_DIM + d];
    }
    __syncthreads();

    const int mg = t / 120;         // 0 or 1 (16 points each)
    const int j0 = t - mg * 120;    // output column 0..119
    const bool act = (t < 240);

    // ================= Fusion 1: cond = fusion(df, te, td) =================
    if (act) {
        // q0 = df@W0, k0 = df@W1, v0 = df@W2  (W0..W2 consecutive)
        proj_pass<3>(Wtd, Btd, XA, PQ, PK0, PV0, mg, j0);
        // k1 = te@W1, v1 = te@W2
        proj_pass<2>(Wtd + 14400, Btd + 120, XB, PK1, PV1, nullptr, mg, j0);
    }
    __syncthreads();
    attention(PQ, PK0, PK1, PV0, PV1, t);
    __syncthreads();
    if (act) {
        // cond = o0@W3 + B3 -> XB (te no longer needed)
        proj_pass<1>(Wtd + 43200, Btd + 360, PQ, XB, nullptr, nullptr, mg, j0);
    }
    __syncthreads();

    // ---- gather static features into XA ----
    for (int e = t; e < PTS_PER_CTA * D_DIM; e += 256) {
        int m = e / D_DIM;
        int d = e - m * D_DIM;
        XA[d * STRIDE + m] = statf[(size_t)vi_s[m] * D_DIM + d];
    }
    __syncthreads();

    // ================ Fusion 2: fused = fusion(sf, cond, sd) ===============
    if (act) {
        proj_pass<3>(Wsd, Bsd, XA, PQ, PK0, PV0, mg, j0);
        proj_pass<2>(Wsd + 14400, Bsd + 120, XB, PK1, PV1, nullptr, mg, j0);
    }
    __syncthreads();
    attention(PQ, PK0, PK1, PV0, PV1, t);
    __syncthreads();
    if (act) {
        proj_out_global(Wsd + 43200, Bsd + 360, PQ, out, ctaBase, val_s, M, mg, j0);
    }
}

extern "C" void kernel_launch(void* const* d_in, const int* in_sizes, int n_in,
                              void* d_out, int out_size) {
    // Positional defaults (reference dict order) ...
    const void* P[10];
    for (int i = 0; i < 10 && i < n_in; ++i) P[i] = d_in[i];
    int M = (n_in > 1) ? in_sizes[1] : 200000;

    // ... then override by size signature (robust to reordered metadata).
    // Unique sizes: pts=600000, times=200000, buf=1048576, temb=24120.
    // Tied sizes keep first-seen order: W (57600 x2), B (480 x2), feats (big x2).
    {
        int nW = 0, nB = 0, nF = 0;
        for (int i = 0; i < n_in && i < 16; ++i) {
            int s = in_sizes[i];
            if (s == 600000)       P[0] = d_in[i];
            else if (s == 200000)  { P[1] = d_in[i]; M = s; }
            else if (s == 1048576) P[2] = d_in[i];
            else if (s == 24120)   P[5] = d_in[i];
            else if (s == 57600)   { P[nW == 0 ? 6 : 8] = d_in[i]; nW++; }
            else if (s == 480)     { P[nB == 0 ? 7 : 9] = d_in[i]; nB++; }
            else if (s > 1048576 && s % 120 == 0) { P[nF == 0 ? 3 : 4] = d_in[i]; nF++; }
        }
    }

    const float* pts   = (const float*)P[0];
    const void*  times = P[1];
    const void*  buf   = P[2];
    const float* statf = (const float*)P[3];
    const float* dynf  = (const float*)P[4];
    const float* temb  = (const float*)P[5];
    const float* Wtd   = (const float*)P[6];
    const float* Btd   = (const float*)P[7];
    const float* Wsd   = (const float*)P[8];
    const float* Bsd   = (const float*)P[9];
    float* out = (float*)d_out;

    cudaFuncSetAttribute(voxel_fused_kernel,
                         cudaFuncAttributeMaxDynamicSharedMemorySize, SMEM_BYTES);

    int grid = (M + PTS_PER_CTA - 1) / PTS_PER_CTA;
    voxel_fused_kernel<<<grid, 256, SMEM_BYTES>>>(
        pts, times, buf, statf, dynf, temb, Wtd, Btd, Wsd, Bsd, out, M);
}

// round 15
// speedup vs baseline: 1.0585x; 1.0585x over previous
#include <cuda_runtime.h>
#include <cuda_bf16.h>

// ---------------------------------------------------------------------------
// VoxelHashTableDynamic fused kernel (fp32, packed f32x2 FMA path)
//
// R15: occupancy push. 16 points/CTA, 6 smem buffers (PV1 aliases XA),
// 51.8KB smem/CTA -> 4 CTAs/SM = 32 warps (50% occ, 2x R13).
// Projection tile: 2 point-pairs x 2 j-cols per thread, warp-major-j
// mapping (mg = t&3) so a-operand LDS are warp broadcasts and each warp's
// weight load touches one 64B line. launch_bounds(256,4) caps regs at 64.
// ---------------------------------------------------------------------------

#define PTS_PER_CTA 16
#define D_DIM       120
#define STRIDE      18            // padded row stride (even -> 8B aligned pairs)
#define BUF_FLOATS  (D_DIM * STRIDE)   // 2160
#define HEADS       8
#define HEAD_DIM    15
#define MOD_T       201
#define HASH_MASK   1048575LL
#define SMEM_BYTES  (6 * BUF_FLOATS * 4 + (3 * PTS_PER_CTA + 2) * 4)

__device__ __forceinline__ unsigned long long splat2(float x) {
    unsigned long long d;
    asm("mov.b64 %0, {%1, %1};" : "=l"(d) : "f"(x));
    return d;
}

__device__ __forceinline__ unsigned long long fma2(unsigned long long a,
                                                   unsigned long long b,
                                                   unsigned long long c) {
    unsigned long long d;
    asm("fma.rn.f32x2 %0, %1, %2, %3;" : "=l"(d) : "l"(a), "l"(b), "l"(c));
    return d;
}

__device__ __forceinline__ float2 unpack2(unsigned long long v) {
    float2 r;
    asm("mov.b64 {%0, %1}, %2;" : "=f"(r.x), "=f"(r.y) : "l"(v));
    return r;
}

// C_w[m][j] = sum_k A[m][k] * W_w[k][j] + B_w[j], for w = 0..NW-1.
// NW weight matrices CONSECUTIVE (stride 14400), biases consecutive (120).
// A_T smem transposed [k][m] (stride 18); outputs transposed [j][m].
// Thread tile: 2 point-pairs (m0 = (t&3)*4) x 2 cols (j0 = (t>>2)*2).
// Lanes of a warp share m0 pattern -> LDS broadcast; 8 distinct j-pairs
// per warp -> weight LDG.64 hits a single 64B line. Threads t>=240 skip.
template <int NW>
__device__ __forceinline__ void proj_pass(const float* __restrict__ W,
                                          const float* __restrict__ Bi,
                                          const float* __restrict__ A_T,
                                          float* C0, float* C1, float* C2,
                                          int m0, int j0) {
    float* Cs[3] = {C0, C1, C2};

    unsigned long long acc[NW][2][2];
#pragma unroll
    for (int w = 0; w < NW; ++w)
#pragma unroll
        for (int jj = 0; jj < 2; ++jj) {
            unsigned long long b2 = splat2(Bi[w * 120 + j0 + jj]);
            acc[w][0][jj] = b2;
            acc[w][1][jj] = b2;
        }

#pragma unroll 2
    for (int k = 0; k < D_DIM; ++k) {
        unsigned long long a2[2];
        const float* arow = A_T + k * STRIDE + m0;
        a2[0] = *reinterpret_cast<const unsigned long long*>(arow);
        a2[1] = *reinterpret_cast<const unsigned long long*>(arow + 2);

#pragma unroll
        for (int w = 0; w < NW; ++w) {
            float2 wf = unpack2(*reinterpret_cast<const unsigned long long*>(
                W + w * 14400 + k * 120 + j0));
            unsigned long long ws0 = splat2(wf.x);
            unsigned long long ws1 = splat2(wf.y);
            acc[w][0][0] = fma2(a2[0], ws0, acc[w][0][0]);
            acc[w][1][0] = fma2(a2[1], ws0, acc[w][1][0]);
            acc[w][0][1] = fma2(a2[0], ws1, acc[w][0][1]);
            acc[w][1][1] = fma2(a2[1], ws1, acc[w][1][1]);
        }
    }

#pragma unroll
    for (int w = 0; w < NW; ++w)
#pragma unroll
        for (int jj = 0; jj < 2; ++jj)
#pragma unroll
            for (int p = 0; p < 2; ++p)
                *reinterpret_cast<unsigned long long*>(
                    Cs[w] + (j0 + jj) * STRIDE + m0 + 2 * p) = acc[w][p][jj];
}

// Final projection straight to gmem with validity masking. Each point row
// gets a packed float2 at column j0 (j0 even, rows 120 floats -> 8B aligned).
__device__ __forceinline__ void proj_out_global(const float* __restrict__ W,
                                                const float* __restrict__ Bi,
                                                const float* __restrict__ A_T,
                                                float* __restrict__ out,
                                                int ctaBase, const int* val_s,
                                                int M, int m0, int j0) {
    unsigned long long acc[2][2];
    {
        unsigned long long b0 = splat2(Bi[j0]);
        unsigned long long b1 = splat2(Bi[j0 + 1]);
        acc[0][0] = b0; acc[1][0] = b0;
        acc[0][1] = b1; acc[1][1] = b1;
    }

#pragma unroll 2
    for (int k = 0; k < D_DIM; ++k) {
        unsigned long long a2[2];
        const float* arow = A_T + k * STRIDE + m0;
        a2[0] = *reinterpret_cast<const unsigned long long*>(arow);
        a2[1] = *reinterpret_cast<const unsigned long long*>(arow + 2);
        float2 wf = unpack2(
            *reinterpret_cast<const unsigned long long*>(W + k * 120 + j0));
        unsigned long long ws0 = splat2(wf.x);
        unsigned long long ws1 = splat2(wf.y);
        acc[0][0] = fma2(a2[0], ws0, acc[0][0]);
        acc[1][0] = fma2(a2[1], ws0, acc[1][0]);
        acc[0][1] = fma2(a2[0], ws1, acc[0][1]);
        acc[1][1] = fma2(a2[1], ws1, acc[1][1]);
    }

#pragma unroll
    for (int p = 0; p < 2; ++p) {
        float2 vj0 = unpack2(acc[p][0]);   // (m even, m odd) at col j0
        float2 vj1 = unpack2(acc[p][1]);   // (m even, m odd) at col j0+1
        int mE = m0 + 2 * p;
        int mO = mE + 1;
        int gE = ctaBase + mE;
        int gO = ctaBase + mO;
        if (gE < M) {
            float2 v = val_s[mE] ? make_float2(vj0.x, vj1.x)
                                 : make_float2(0.f, 0.f);
            *reinterpret_cast<float2*>(out + (size_t)gE * 120 + j0) = v;
        }
        if (gO < M) {
            float2 v = val_s[mO] ? make_float2(vj0.y, vj1.y)
                                 : make_float2(0.f, 0.f);
            *reinterpret_cast<float2*>(out + (size_t)gO * 120 + j0) = v;
        }
    }
}

// 2-token attention per (point, head): 128 tasks = 16 points * 8 heads.
__device__ __forceinline__ void attention(float* PQ, const float* PK0,
                                          const float* PK1, const float* PV0,
                                          const float* PV1, int t) {
    if (t >= PTS_PER_CTA * HEADS) return;
    const float SC = 0.25819888974716113f;  // 1/sqrt(15)
    int m = t & (PTS_PER_CTA - 1);
    int h = t / PTS_PER_CTA;
    int base = h * HEAD_DIM;
    float s00 = 0.f, s01 = 0.f;
#pragma unroll
    for (int d = 0; d < HEAD_DIM; ++d) {
        int idx = (base + d) * STRIDE + m;
        float q = PQ[idx];
        s00 += q * PK0[idx];
        s01 += q * PK1[idx];
    }
    float p00 = 1.0f / (1.0f + __expf((s01 - s00) * SC));
    float p01 = 1.0f - p00;
#pragma unroll
    for (int d = 0; d < HEAD_DIM; ++d) {
        int idx = (base + d) * STRIDE + m;
        PQ[idx] = p00 * PV0[idx] + p01 * PV1[idx];
    }
}

__global__ __launch_bounds__(256, 4) void voxel_fused_kernel(
    const float* __restrict__ pts, const void* __restrict__ times_raw,
    const void* __restrict__ buf_raw, const float* __restrict__ statf,
    const float* __restrict__ dynf, const float* __restrict__ temb,
    const float* __restrict__ Wtd, const float* __restrict__ Btd,
    const float* __restrict__ Wsd, const float* __restrict__ Bsd,
    float* __restrict__ out, int M) {
    extern __shared__ float sm[];
    // 6 buffers; PV1 aliases B0 (XA is dead after the first proj_pass<3>).
    float* B0 = sm;                    // XA (df / sf), later PV1
    float* B1 = sm + 1 * BUF_FLOATS;   // XB (te), later cond
    float* B2 = sm + 2 * BUF_FLOATS;   // PQ / attention out
    float* B3 = sm + 3 * BUF_FLOATS;   // PK0
    float* B4 = sm + 4 * BUF_FLOATS;   // PV0
    float* B5 = sm + 5 * BUF_FLOATS;   // PK1
    int* vi_s  = (int*)(sm + 6 * BUF_FLOATS);
    int* ti_s  = vi_s + PTS_PER_CTA;
    int* val_s = ti_s + PTS_PER_CTA;
    int* fl    = val_s + PTS_PER_CTA;  // fl[0]=buf is int32, fl[1]=times is int32

    const int t = threadIdx.x;
    const int ctaBase = blockIdx.x * PTS_PER_CTA;

    // ---- dtype probe: odd 32-bit words are sign/zero-extension iff int64 ----
    if (t < 2) fl[t] = 0;
    __syncthreads();
    if (t < 64) {
        const int* b32 = (const int*)buf_raw;
        int bad = 0;
#pragma unroll
        for (int r = 0; r < 2; ++r) {
            int w = b32[2 * (t + 64 * r) + 1];
            if (w != 0 && w != -1) bad = 1;
        }
        if (bad) atomicOr(&fl[0], 1);
        const int* q32 = (const int*)times_raw;
        int badt = 0;
#pragma unroll
        for (int r = 0; r < 4; ++r) {
            if (q32[2 * (t + 64 * r) + 1] != 0) badt = 1;
        }
        if (badt) atomicOr(&fl[1], 1);
    }
    __syncthreads();
    const bool buf32 = fl[0] != 0;
    const bool tim32 = fl[1] != 0;

    // ---- per-point metadata: hash lookup, validity, time index ----
    if (t < PTS_PER_CTA) {
        int g = ctaBase + t;
        int vi = 0, va = 0, ti = 0;
        if (g < M) {
            float px = pts[3 * g + 0];
            float py = pts[3 * g + 1];
            float pz = pts[3 * g + 2];
            // must match reference bit-for-bit: f32 IEEE divide, then floor
            long long g0 = (long long)floorf(__fdiv_rn(px, 0.1f));
            long long g1 = (long long)floorf(__fdiv_rn(py, 0.1f));
            long long g2 = (long long)floorf(__fdiv_rn(pz, 0.1f));
            long long h =
                (g0 * 73856093LL + g1 * 19349669LL + g2 * 83492791LL) & HASH_MASK;
            long long v = buf32 ? (long long)((const int*)buf_raw)[h]
                                : ((const long long*)buf_raw)[h];
            va = (v >= 0) ? 1 : 0;
            vi = va ? (int)v : 0;
            long long tv = tim32 ? (long long)((const int*)times_raw)[g]
                                 : ((const long long*)times_raw)[g];
            ti = (int)(tv % MOD_T);
            if (ti < 0) ti += MOD_T;
        }
        vi_s[t] = vi;
        ti_s[t] = ti;
        val_s[t] = va;
    }
    __syncthreads();

    // ---- gather dynamic features + time embeddings (transposed) ----
    for (int e = t; e < PTS_PER_CTA * D_DIM; e += 256) {
        int m = e / D_DIM;
        int d = e - m * D_DIM;
        B0[d * STRIDE + m] = dynf[(size_t)vi_s[m] * D_DIM + d];
        B1[d * STRIDE + m] = temb[(size_t)ti_s[m] * D_DIM + d];
    }
    __syncthreads();

    const int m0 = (t & 3) * 4;     // 2 point-pairs per thread
    const int j0 = (t >> 2) * 2;    // 2 output columns (j0 < 120 for t < 240)
    const bool act = (t < 240);

    // ================= Fusion 1: cond = fusion(df, te, td) =================
    if (act) {
        // q0 = df@W0, k0 = df@W1, v0 = df@W2  (reads B0)
        proj_pass<3>(Wtd, Btd, B0, B2, B3, B4, m0, j0);
    }
    __syncthreads();   // B0 reads complete before aliasing as PV1
    if (act) {
        // k1 = te@W1 -> B5, v1 = te@W2 -> B0 (PV1 aliases XA)
        proj_pass<2>(Wtd + 14400, Btd + 120, B1, B5, B0, nullptr, m0, j0);
    }
    __syncthreads();
    attention(B2, B3, B5, B4, B0, t);
    __syncthreads();
    if (act) {
        // cond = o0@W3 + B3 -> B1 (te no longer needed)
        proj_pass<1>(Wtd + 43200, Btd + 360, B2, B1, nullptr, nullptr, m0, j0);
    }
    __syncthreads();

    // ---- gather static features into B0 (PV1 consumed) ----
    for (int e = t; e < PTS_PER_CTA * D_DIM; e += 256) {
        int m = e / D_DIM;
        int d = e - m * D_DIM;
        B0[d * STRIDE + m] = statf[(size_t)vi_s[m] * D_DIM + d];
    }
    __syncthreads();

    // ================ Fusion 2: fused = fusion(sf, cond, sd) ===============
    if (act) {
        proj_pass<3>(Wsd, Bsd, B0, B2, B3, B4, m0, j0);
    }
    __syncthreads();
    if (act) {
        proj_pass<2>(Wsd + 14400, Bsd + 120, B1, B5, B0, nullptr, m0, j0);
    }
    __syncthreads();
    attention(B2, B3, B5, B4, B0, t);
    __syncthreads();
    if (act) {
        proj_out_global(Wsd + 43200, Bsd + 360, B2, out, ctaBase, val_s, M,
                        m0, j0);
    }
}

extern "C" void kernel_launch(void* const* d_in, const int* in_sizes, int n_in,
                              void* d_out, int out_size) {
    // Positional defaults (reference dict order) ...
    const void* P[10];
    for (int i = 0; i < 10 && i < n_in; ++i) P[i] = d_in[i];
    int M = (n_in > 1) ? in_sizes[1] : 200000;

    // ... then override by size signature (robust to reordered metadata).
    {
        int nW = 0, nB = 0, nF = 0;
        for (int i = 0; i < n_in && i < 16; ++i) {
            int s = in_sizes[i];
            if (s == 600000)       P[0] = d_in[i];
            else if (s == 200000)  { P[1] = d_in[i]; M = s; }
            else if (s == 1048576) P[2] = d_in[i];
            else if (s == 24120)   P[5] = d_in[i];
            else if (s == 57600)   { P[nW == 0 ? 6 : 8] = d_in[i]; nW++; }
            else if (s == 480)     { P[nB == 0 ? 7 : 9] = d_in[i]; nB++; }
            else if (s > 1048576 && s % 120 == 0) { P[nF == 0 ? 3 : 4] = d_in[i]; nF++; }
        }
    }

    const float* pts   = (const float*)P[0];
    const void*  times = P[1];
    const void*  buf   = P[2];
    const float* statf = (const float*)P[3];
    const float* dynf  = (const float*)P[4];
    const float* temb  = (const float*)P[5];
    const float* Wtd   = (const float*)P[6];
    const float* Btd   = (const float*)P[7];
    const float* Wsd   = (const float*)P[8];
    const float* Bsd   = (const float*)P[9];
    float* out = (float*)d_out;

    cudaFuncSetAttribute(voxel_fused_kernel,
                         cudaFuncAttributeMaxDynamicSharedMemorySize, SMEM_BYTES);

    int grid = (M + PTS_PER_CTA - 1) / PTS_PER_CTA;
    voxel_fused_kernel<<<grid, 256, SMEM_BYTES>>>(
        pts, times, buf, statf, dynf, temb, Wtd, Btd, Wsd, Bsd, out, M);
}